// round 9
// baseline (speedup 1.0000x reference)
#include <cuda_runtime.h>
#include <cuda_bf16.h>
#include <stdint.h>
#include <math.h>

#define BB 16
#define NN 1024
#define FIN 256
#define FOUT 256
#define HH 8
#define ALPHA 0.2f

// Scratch (device globals; no allocations allowed)
__device__ float g_Wh[(size_t)BB * HH * NN * FOUT];
__device__ __nv_bfloat16 g_Whb[(size_t)BB * HH * NN * FOUT];
__device__ float g_ei[BB * HH * NN];
__device__ float g_ejb[BB * HH * NN];
__device__ __nv_bfloat16 g_hb[(size_t)8 * 16384 * 32];
__device__ __nv_bfloat16 g_hs[(size_t)8 * 16384 * 32];
__device__ __nv_bfloat16 g_wb[(size_t)8 * 2048 * 32];
__device__ __nv_bfloat16 g_ws[(size_t)8 * 2048 * 32];
// prefix-scan attention scratch
__device__ float g_ejs[BB * HH * NN];                       // sorted ej
__device__ float g_U[(size_t)BB * HH * 1025 * FOUT];        // suffix sums
__device__ float g_V[(size_t)BB * HH * 1025 * FOUT];        // prefix sums
__device__ float g_usum[BB * HH * 1025];
__device__ float g_vsum[BB * HH * 1025];

#define MMA_BF16(c, a0, a1, a2, a3, b0, b1) \
    asm volatile("mma.sync.aligned.m16n8k16.row.col.f32.bf16.bf16.f32 " \
        "{%0,%1,%2,%3}, {%4,%5,%6,%7}, {%8,%9}, {%0,%1,%2,%3};" \
        : "+f"((c)[0]), "+f"((c)[1]), "+f"((c)[2]), "+f"((c)[3]) \
        : "r"(a0), "r"(a1), "r"(a2), "r"(a3), "r"(b0), "r"(b1))

#define PACK_BF16X2(r, lo, hi) \
    asm("cvt.rn.bf16x2.f32 %0, %1, %2;" : "=r"(r) : "f"(hi), "f"(lo))

#define CP16(dst, src) \
    asm volatile("cp.async.cg.shared.global [%0], [%1], 16;" :: "r"(dst), "l"(src) : "memory")
#define CP_COMMIT() asm volatile("cp.async.commit_group;" ::: "memory")
#define CP_WAIT1()  asm volatile("cp.async.wait_group 1;" ::: "memory")
#define CP_WAIT0()  asm volatile("cp.async.wait_group 0;" ::: "memory")

__device__ __forceinline__ uint32_t smem_u32(const void* p) {
    uint32_t a;
    asm("{ .reg .u64 t; cvta.to.shared.u64 t, %1; cvt.u32.u64 %0, t; }"
        : "=r"(a) : "l"(p));
    return a;
}
__device__ __forceinline__ void ldsm_x4(uint32_t& r0, uint32_t& r1,
                                        uint32_t& r2, uint32_t& r3, uint32_t addr) {
    asm volatile("ldmatrix.sync.aligned.m8n8.x4.shared.b16 {%0,%1,%2,%3}, [%4];"
                 : "=r"(r0), "=r"(r1), "=r"(r2), "=r"(r3) : "r"(addr));
}

// ---------------------------------------------------------------------------
// Prep: split fp32 -> big/small bf16, k-tiled [kt][row][32]
// ---------------------------------------------------------------------------
__global__ void split_h_kernel(const float* __restrict__ src)
{
    const int m = blockIdx.x;
    const int k = threadIdx.x;
    float x = src[(size_t)m * 256 + k];
    __nv_bfloat16 b = __float2bfloat16(x);
    __nv_bfloat16 s = __float2bfloat16(x - __bfloat162float(b));
    size_t idx = ((size_t)(k >> 5) * 16384 + m) * 32 + (k & 31);
    g_hb[idx] = b;
    g_hs[idx] = s;
}
__global__ void split_w_kernel(const float* __restrict__ src)
{
    const int j = blockIdx.x;
    const int k = threadIdx.x;
    float x = src[(size_t)j * 256 + k];
    __nv_bfloat16 b = __float2bfloat16(x);
    __nv_bfloat16 s = __float2bfloat16(x - __bfloat162float(b));
    size_t idx = ((size_t)(k >> 5) * 2048 + j) * 32 + (k & 31);
    g_wb[idx] = b;
    g_ws[idx] = s;
}

// ---------------------------------------------------------------------------
// Kernel 1: Wh = h @ W^T + bW via 3xBF16 m16n8k16 + cp.async (unchanged R8)
// ---------------------------------------------------------------------------
#define G1_PLANE_B 8192
#define G1_BUF (4 * G1_PLANE_B)
#define G1_SMEM (3 * G1_BUF)

__global__ void __launch_bounds__(256, 2) gemm1_cp_kernel(const float* __restrict__ bWp)
{
    extern __shared__ char gsm[];
    const uint32_t sbuf = smem_u32(gsm);

    const int tid  = threadIdx.x;
    const int lane = tid & 31;
    const int wid  = tid >> 5;
    const int mw   = wid & 1;
    const int nw   = wid >> 1;
    const int tg   = lane & 3;
    const int g    = lane >> 2;
    const int m0   = blockIdx.x * 128;
    const int j0   = blockIdx.y * 128;

    const int lrow = tid & 127;
    const int kh   = tid >> 7;
    const int swzr = (lrow & 3) ^ ((lrow >> 2) & 3);
    const uint32_t d0 = (uint32_t)lrow * 64 + (((2 * kh)     ^ swzr) << 4);
    const uint32_t d1 = (uint32_t)lrow * 64 + (((2 * kh + 1) ^ swzr) << 4);
    const char* srcAb = (const char*)g_hb + ((size_t)(m0 + lrow)) * 64 + kh * 32;
    const char* srcAs = (const char*)g_hs + ((size_t)(m0 + lrow)) * 64 + kh * 32;
    const char* srcBb = (const char*)g_wb + ((size_t)(j0 + lrow)) * 64 + kh * 32;
    const char* srcBs = (const char*)g_ws + ((size_t)(j0 + lrow)) * 64 + kh * 32;

    const int lro  = (lane & 7) + ((lane >> 3) & 1) * 8;
    const int lkc  = lane >> 4;
    const int swzL = (lro & 3) ^ ((lro >> 2) & 3);

    float acc[4][4][4];
#pragma unroll
    for (int mi = 0; mi < 4; mi++)
#pragma unroll
        for (int f = 0; f < 4; f++)
#pragma unroll
            for (int c = 0; c < 4; c++) acc[mi][f][c] = 0.f;

    {
        const uint32_t bb = sbuf;
        CP16(bb + d0, srcAb); CP16(bb + d1, srcAb + 16);
        CP16(bb + G1_PLANE_B + d0, srcAs); CP16(bb + G1_PLANE_B + d1, srcAs + 16);
        CP16(bb + 2 * G1_PLANE_B + d0, srcBb); CP16(bb + 2 * G1_PLANE_B + d1, srcBb + 16);
        CP16(bb + 3 * G1_PLANE_B + d0, srcBs); CP16(bb + 3 * G1_PLANE_B + d1, srcBs + 16);
        CP_COMMIT();
    }

    for (int kt = 0; kt < 8; kt++) {
        if (kt < 7) {
            const uint32_t bb = sbuf + ((kt + 1) % 3) * G1_BUF;
            const size_t offA = (size_t)(kt + 1) * (16384 * 64);
            const size_t offB = (size_t)(kt + 1) * (2048 * 64);
            CP16(bb + d0, srcAb + offA); CP16(bb + d1, srcAb + offA + 16);
            CP16(bb + G1_PLANE_B + d0, srcAs + offA); CP16(bb + G1_PLANE_B + d1, srcAs + offA + 16);
            CP16(bb + 2 * G1_PLANE_B + d0, srcBb + offB); CP16(bb + 2 * G1_PLANE_B + d1, srcBb + offB + 16);
            CP16(bb + 3 * G1_PLANE_B + d0, srcBs + offB); CP16(bb + 3 * G1_PLANE_B + d1, srcBs + offB + 16);
            CP_COMMIT();
            CP_WAIT1();
        } else {
            CP_WAIT0();
        }
        __syncthreads();

        const uint32_t base = sbuf + (kt % 3) * G1_BUF;
        const uint32_t sAb = base;
        const uint32_t sAs = base + G1_PLANE_B;
        const uint32_t sBb = base + 2 * G1_PLANE_B;
        const uint32_t sBs = base + 3 * G1_PLANE_B;

#pragma unroll
        for (int ks = 0; ks < 2; ks++) {
            const int kc = 2 * ks + lkc;
            const uint32_t csw = (uint32_t)((kc ^ swzL) << 4);

            uint32_t ab[4][4], as_[4][4];
#pragma unroll
            for (int mi = 0; mi < 4; mi++) {
                uint32_t ro = (uint32_t)(mw * 64 + mi * 16 + lro) * 64 + csw;
                ldsm_x4(ab[mi][0], ab[mi][1], ab[mi][2], ab[mi][3], sAb + ro);
                ldsm_x4(as_[mi][0], as_[mi][1], as_[mi][2], as_[mi][3], sAs + ro);
            }
            uint32_t bbg[2][4], bsm[2][4];
#pragma unroll
            for (int fp = 0; fp < 2; fp++) {
                uint32_t ro = (uint32_t)(nw * 32 + fp * 16 + lro) * 64 + csw;
                ldsm_x4(bbg[fp][0], bbg[fp][1], bbg[fp][2], bbg[fp][3], sBb + ro);
                ldsm_x4(bsm[fp][0], bsm[fp][1], bsm[fp][2], bsm[fp][3], sBs + ro);
            }
#pragma unroll
            for (int fp = 0; fp < 2; fp++) {
#pragma unroll
                for (int sub = 0; sub < 2; sub++) {
                    const int f = fp * 2 + sub;
                    const uint32_t b0g = bbg[fp][sub], b1g = bbg[fp][2 + sub];
                    const uint32_t b0s = bsm[fp][sub], b1s = bsm[fp][2 + sub];
#pragma unroll
                    for (int mi = 0; mi < 4; mi++) {
                        MMA_BF16(acc[mi][f], ab[mi][0], ab[mi][1], ab[mi][2], ab[mi][3], b0g, b1g);
                        MMA_BF16(acc[mi][f], as_[mi][0], as_[mi][1], as_[mi][2], as_[mi][3], b0g, b1g);
                        MMA_BF16(acc[mi][f], ab[mi][0], ab[mi][1], ab[mi][2], ab[mi][3], b0s, b1s);
                    }
                }
            }
        }
    }

#pragma unroll
    for (int f = 0; f < 4; f++) {
        const int c = j0 + nw * 32 + f * 8 + tg * 2;
        const float bw0 = bWp[c];
        const float bw1 = bWp[c + 1];
        const int h = c >> 8;
        const int o = c & 255;
#pragma unroll
        for (int mi = 0; mi < 4; mi++) {
            int r0 = m0 + mw * 64 + mi * 16 + g;
            int b0i = r0 >> 10, n0i = r0 & 1023;
            int r1 = r0 + 8;
            int b1i = r1 >> 10, n1i = r1 & 1023;
            float2 v0, v1;
            v0.x = acc[mi][f][0] + bw0; v0.y = acc[mi][f][1] + bw1;
            v1.x = acc[mi][f][2] + bw0; v1.y = acc[mi][f][3] + bw1;
            size_t i0 = ((size_t)(b0i * HH + h) * NN + n0i) * FOUT + o;
            size_t i1 = ((size_t)(b1i * HH + h) * NN + n1i) * FOUT + o;
            *(float2*)(g_Wh + i0) = v0;
            *(float2*)(g_Wh + i1) = v1;
            uint32_t u0, u1;
            PACK_BF16X2(u0, v0.x, v0.y);
            PACK_BF16X2(u1, v1.x, v1.y);
            *(uint32_t*)((char*)g_Whb + i0 * 2) = u0;
            *(uint32_t*)((char*)g_Whb + i1 * 2) = u1;
        }
    }
}

// ---------------------------------------------------------------------------
// Kernel 2: ei / ejb projections (unchanged)
// ---------------------------------------------------------------------------
__global__ void __launch_bounds__(256) score_kernel(const float* __restrict__ a1,
                                                    const float* __restrict__ a2,
                                                    const float* __restrict__ bA)
{
    const int warp = threadIdx.x >> 5;
    const int lane = threadIdx.x & 31;
    const int row = blockIdx.x * 8 + warp;
    const int h = (row >> 10) & (HH - 1);

    const float4* wr = (const float4*)(g_Wh + (size_t)row * FOUT);
    const float4* p1 = (const float4*)(a1 + h * FOUT);
    const float4* p2 = (const float4*)(a2 + h * FOUT);

    float s1 = 0.f, s2 = 0.f;
#pragma unroll
    for (int u = 0; u < 2; u++) {
        float4 v = wr[lane + u * 32];
        float4 x = p1[lane + u * 32];
        float4 y = p2[lane + u * 32];
        s1 += v.x * x.x + v.y * x.y + v.z * x.z + v.w * x.w;
        s2 += v.x * y.x + v.y * y.y + v.z * y.z + v.w * y.w;
    }
#pragma unroll
    for (int off = 16; off > 0; off >>= 1) {
        s1 += __shfl_xor_sync(0xffffffffu, s1, off);
        s2 += __shfl_xor_sync(0xffffffffu, s2, off);
    }
    if (lane == 0) {
        g_ei[row] = s1;
        g_ejb[row] = s2 + bA[h];
    }
}

// ---------------------------------------------------------------------------
// Kernel 3a: per-bh bitonic sort of ej (key+index) then prefix/suffix scans:
//   V[s][o] = sum_{r<s}  exp(.2*ej_r) * Whb[j_r][o]   (s = 0..1024)
//   U[s][o] = sum_{r>=s} exp(ej_r)    * Whb[j_r][o]
// plus scalar vsum/usum. One block per bh, 256 threads (thread = o column).
// ---------------------------------------------------------------------------
__global__ void __launch_bounds__(256) sortscan_kernel()
{
    __shared__ float key[1024];
    __shared__ int   sidx[1024];
    __shared__ float su[1024];
    __shared__ float sv[1024];

    const int bh = blockIdx.x;
    const int tid = threadIdx.x;

    for (int t = tid; t < 1024; t += 256) {
        key[t] = g_ejb[bh * 1024 + t];
        sidx[t] = t;
    }
    __syncthreads();

    // bitonic sort ascending (deterministic)
    for (int k = 2; k <= 1024; k <<= 1) {
        for (int j = k >> 1; j > 0; j >>= 1) {
            for (int t = tid; t < 1024; t += 256) {
                int p = t ^ j;
                if (p > t) {
                    bool up = ((t & k) == 0);
                    float a = key[t], b = key[p];
                    if ((a > b) == up) {
                        key[t] = b; key[p] = a;
                        int ia = sidx[t]; sidx[t] = sidx[p]; sidx[p] = ia;
                    }
                }
            }
            __syncthreads();
        }
    }

    for (int t = tid; t < 1024; t += 256) {
        float e = key[t];
        su[t] = __expf(e);
        sv[t] = __expf(ALPHA * e);
        g_ejs[bh * 1024 + t] = e;
    }
    __syncthreads();

    const __nv_bfloat16* wb = g_Whb + (size_t)bh * (NN * FOUT);
    float* Vb = g_V + (size_t)bh * 1025 * FOUT;
    float* Ub = g_U + (size_t)bh * 1025 * FOUT;

    // prefix pass (V)
    float acc = 0.f, ssum = 0.f;
    Vb[tid] = 0.f;                                   // V[0] = 0
    if (tid == 0) g_vsum[bh * 1025] = 0.f;
    for (int r = 0; r < 1024; r++) {
        int j = sidx[r];
        float vr = sv[r];
        float w = __bfloat162float(wb[(size_t)j * FOUT + tid]);
        acc = fmaf(vr, w, acc);
        ssum += vr;
        Vb[(size_t)(r + 1) * FOUT + tid] = acc;
        if (tid == 0) g_vsum[bh * 1025 + r + 1] = ssum;
    }

    // suffix pass (U)
    acc = 0.f; ssum = 0.f;
    Ub[(size_t)1024 * FOUT + tid] = 0.f;             // U[1024] = 0
    if (tid == 0) g_usum[bh * 1025 + 1024] = 0.f;
    for (int r = 1023; r >= 0; r--) {
        int j = sidx[r];
        float ur = su[r];
        float w = __bfloat162float(wb[(size_t)j * FOUT + tid]);
        acc = fmaf(ur, w, acc);
        ssum += ur;
        Ub[(size_t)r * FOUT + tid] = acc;
        if (tid == 0) g_usum[bh * 1025 + r] = ssum;
    }
}

// ---------------------------------------------------------------------------
// Kernel 3b: gather + epilogue. Block = (bh, 128-row tile), 256 threads.
// Row i: s = upper_bound(sorted ej, -ei);
// out = sigmoid(relu((e^{ei} U[s] + e^{.2ei} V[s]) / (e^{ei} usum[s] + e^{.2ei} vsum[s])))
// ---------------------------------------------------------------------------
__global__ void __launch_bounds__(256) gather_kernel(float* __restrict__ out)
{
    __shared__ float sej[1024];
    __shared__ float sAi[128], sBi[128], sil[128];
    __shared__ int   ssx[128];

    const int bh = blockIdx.x >> 3;
    const int it = blockIdx.x & 7;
    const int tid = threadIdx.x;

    for (int t = tid; t < 1024; t += 256)
        sej[t] = g_ejs[bh * 1024 + t];
    __syncthreads();

    if (tid < 128) {
        int row = it * 128 + tid;
        float ei = g_ei[bh * 1024 + row];
        float Ai = __expf(ei);
        float Bi = __expf(ALPHA * ei);
        float t = -ei;
        int lo = 0, hi = 1024;
        while (lo < hi) {
            int mid = (lo + hi) >> 1;
            if (sej[mid] <= t) lo = mid + 1; else hi = mid;
        }
        int s = lo;
        float l = Ai * g_usum[bh * 1025 + s] + Bi * g_vsum[bh * 1025 + s];
        sAi[tid] = Ai; sBi[tid] = Bi; ssx[tid] = s; sil[tid] = 1.f / l;
    }
    __syncthreads();

    const float* Ub = g_U + (size_t)bh * 1025 * FOUT;
    const float* Vb = g_V + (size_t)bh * 1025 * FOUT;
    const int b = bh >> 3, h = bh & 7;

    for (int r0 = 0; r0 < 128; r0++) {
        int s = ssx[r0];
        float Ai = sAi[r0], Bi = sBi[r0], il = sil[r0];
        float uo = Ub[(size_t)s * FOUT + tid];
        float vo = Vb[(size_t)s * FOUT + tid];
        float x = (Ai * uo + Bi * vo) * il;
        x = fmaxf(x, 0.f);
        float y = 1.f / (1.f + __expf(-x));
        out[(size_t)(b * NN + it * 128 + r0) * (HH * FOUT) + h * FOUT + tid] = y;
    }
}

// ---------------------------------------------------------------------------
extern "C" void kernel_launch(void* const* d_in, const int* in_sizes, int n_in,
                              void* d_out, int out_size)
{
    (void)in_sizes; (void)n_in; (void)out_size;
    const float* h_in = (const float*)d_in[0];
    const float* W    = (const float*)d_in[1];
    const float* bW   = (const float*)d_in[2];
    const float* a1   = (const float*)d_in[3];
    const float* a2   = (const float*)d_in[4];
    const float* bA   = (const float*)d_in[5];
    float* out = (float*)d_out;

    split_h_kernel<<<16384, 256>>>(h_in);
    split_w_kernel<<<2048, 256>>>(W);

    cudaFuncSetAttribute(gemm1_cp_kernel,
                         cudaFuncAttributeMaxDynamicSharedMemorySize, G1_SMEM);
    gemm1_cp_kernel<<<dim3(128, 16), 256, G1_SMEM>>>(bW);

    score_kernel<<<(BB * HH * NN) / 8, 256>>>(a1, a2, bA);

    sortscan_kernel<<<BB * HH, 256>>>();
    gather_kernel<<<BB * HH * 8, 256>>>(out);
}

// round 10
// speedup vs baseline: 1.2559x; 1.2559x over previous
#include <cuda_runtime.h>
#include <cuda_bf16.h>
#include <stdint.h>
#include <math.h>

#define BB 16
#define NN 1024
#define FIN 256
#define FOUT 256
#define HH 8
#define ALPHA 0.2f

// Scratch (device globals; no allocations allowed)
__device__ float g_Wh[(size_t)BB * HH * NN * FOUT];
__device__ __nv_bfloat16 g_Whb[(size_t)BB * HH * NN * FOUT];
__device__ float g_ei[BB * HH * NN];
__device__ float g_ejb[BB * HH * NN];
__device__ __nv_bfloat16 g_hb[(size_t)8 * 16384 * 32];
__device__ __nv_bfloat16 g_hs[(size_t)8 * 16384 * 32];
__device__ __nv_bfloat16 g_wb[(size_t)8 * 2048 * 32];
__device__ __nv_bfloat16 g_ws[(size_t)8 * 2048 * 32];

#define MMA_BF16(c, a0, a1, a2, a3, b0, b1) \
    asm volatile("mma.sync.aligned.m16n8k16.row.col.f32.bf16.bf16.f32 " \
        "{%0,%1,%2,%3}, {%4,%5,%6,%7}, {%8,%9}, {%0,%1,%2,%3};" \
        : "+f"((c)[0]), "+f"((c)[1]), "+f"((c)[2]), "+f"((c)[3]) \
        : "r"(a0), "r"(a1), "r"(a2), "r"(a3), "r"(b0), "r"(b1))

#define PACK_BF16X2(r, lo, hi) \
    asm("cvt.rn.bf16x2.f32 %0, %1, %2;" : "=r"(r) : "f"(hi), "f"(lo))

#define CP16(dst, src) \
    asm volatile("cp.async.cg.shared.global [%0], [%1], 16;" :: "r"(dst), "l"(src) : "memory")
#define CP_COMMIT() asm volatile("cp.async.commit_group;" ::: "memory")
#define CP_WAIT1()  asm volatile("cp.async.wait_group 1;" ::: "memory")
#define CP_WAIT0()  asm volatile("cp.async.wait_group 0;" ::: "memory")

__device__ __forceinline__ uint32_t smem_u32(const void* p) {
    uint32_t a;
    asm("{ .reg .u64 t; cvta.to.shared.u64 t, %1; cvt.u32.u64 %0, t; }"
        : "=r"(a) : "l"(p));
    return a;
}
__device__ __forceinline__ void ldsm_x4(uint32_t& r0, uint32_t& r1,
                                        uint32_t& r2, uint32_t& r3, uint32_t addr) {
    asm volatile("ldmatrix.sync.aligned.m8n8.x4.shared.b16 {%0,%1,%2,%3}, [%4];"
                 : "=r"(r0), "=r"(r1), "=r"(r2), "=r"(r3) : "r"(addr));
}

// ---------------------------------------------------------------------------
// Prep: split fp32 -> big/small bf16, k-tiled [kt][row][32]
// ---------------------------------------------------------------------------
__global__ void split_h_kernel(const float* __restrict__ src)
{
    const int m = blockIdx.x;
    const int k = threadIdx.x;
    float x = src[(size_t)m * 256 + k];
    __nv_bfloat16 b = __float2bfloat16(x);
    __nv_bfloat16 s = __float2bfloat16(x - __bfloat162float(b));
    size_t idx = ((size_t)(k >> 5) * 16384 + m) * 32 + (k & 31);
    g_hb[idx] = b;
    g_hs[idx] = s;
}
__global__ void split_w_kernel(const float* __restrict__ src)
{
    const int j = blockIdx.x;
    const int k = threadIdx.x;
    float x = src[(size_t)j * 256 + k];
    __nv_bfloat16 b = __float2bfloat16(x);
    __nv_bfloat16 s = __float2bfloat16(x - __bfloat162float(b));
    size_t idx = ((size_t)(k >> 5) * 2048 + j) * 32 + (k & 31);
    g_wb[idx] = b;
    g_ws[idx] = s;
}

// ---------------------------------------------------------------------------
// Kernel 1: Wh = h @ W^T + bW via 3xBF16 m16n8k16 + cp.async (unchanged R8)
// ---------------------------------------------------------------------------
#define G1_PLANE_B 8192
#define G1_BUF (4 * G1_PLANE_B)
#define G1_SMEM (3 * G1_BUF)

__global__ void __launch_bounds__(256, 2) gemm1_cp_kernel(const float* __restrict__ bWp)
{
    extern __shared__ char gsm[];
    const uint32_t sbuf = smem_u32(gsm);

    const int tid  = threadIdx.x;
    const int lane = tid & 31;
    const int wid  = tid >> 5;
    const int mw   = wid & 1;
    const int nw   = wid >> 1;
    const int tg   = lane & 3;
    const int g    = lane >> 2;
    const int m0   = blockIdx.x * 128;
    const int j0   = blockIdx.y * 128;

    const int lrow = tid & 127;
    const int kh   = tid >> 7;
    const int swzr = (lrow & 3) ^ ((lrow >> 2) & 3);
    const uint32_t d0 = (uint32_t)lrow * 64 + (((2 * kh)     ^ swzr) << 4);
    const uint32_t d1 = (uint32_t)lrow * 64 + (((2 * kh + 1) ^ swzr) << 4);
    const char* srcAb = (const char*)g_hb + ((size_t)(m0 + lrow)) * 64 + kh * 32;
    const char* srcAs = (const char*)g_hs + ((size_t)(m0 + lrow)) * 64 + kh * 32;
    const char* srcBb = (const char*)g_wb + ((size_t)(j0 + lrow)) * 64 + kh * 32;
    const char* srcBs = (const char*)g_ws + ((size_t)(j0 + lrow)) * 64 + kh * 32;

    const int lro  = (lane & 7) + ((lane >> 3) & 1) * 8;
    const int lkc  = lane >> 4;
    const int swzL = (lro & 3) ^ ((lro >> 2) & 3);

    float acc[4][4][4];
#pragma unroll
    for (int mi = 0; mi < 4; mi++)
#pragma unroll
        for (int f = 0; f < 4; f++)
#pragma unroll
            for (int c = 0; c < 4; c++) acc[mi][f][c] = 0.f;

    {
        const uint32_t bb = sbuf;
        CP16(bb + d0, srcAb); CP16(bb + d1, srcAb + 16);
        CP16(bb + G1_PLANE_B + d0, srcAs); CP16(bb + G1_PLANE_B + d1, srcAs + 16);
        CP16(bb + 2 * G1_PLANE_B + d0, srcBb); CP16(bb + 2 * G1_PLANE_B + d1, srcBb + 16);
        CP16(bb + 3 * G1_PLANE_B + d0, srcBs); CP16(bb + 3 * G1_PLANE_B + d1, srcBs + 16);
        CP_COMMIT();
    }

    for (int kt = 0; kt < 8; kt++) {
        if (kt < 7) {
            const uint32_t bb = sbuf + ((kt + 1) % 3) * G1_BUF;
            const size_t offA = (size_t)(kt + 1) * (16384 * 64);
            const size_t offB = (size_t)(kt + 1) * (2048 * 64);
            CP16(bb + d0, srcAb + offA); CP16(bb + d1, srcAb + offA + 16);
            CP16(bb + G1_PLANE_B + d0, srcAs + offA); CP16(bb + G1_PLANE_B + d1, srcAs + offA + 16);
            CP16(bb + 2 * G1_PLANE_B + d0, srcBb + offB); CP16(bb + 2 * G1_PLANE_B + d1, srcBb + offB + 16);
            CP16(bb + 3 * G1_PLANE_B + d0, srcBs + offB); CP16(bb + 3 * G1_PLANE_B + d1, srcBs + offB + 16);
            CP_COMMIT();
            CP_WAIT1();
        } else {
            CP_WAIT0();
        }
        __syncthreads();

        const uint32_t base = sbuf + (kt % 3) * G1_BUF;
        const uint32_t sAb = base;
        const uint32_t sAs = base + G1_PLANE_B;
        const uint32_t sBb = base + 2 * G1_PLANE_B;
        const uint32_t sBs = base + 3 * G1_PLANE_B;

#pragma unroll
        for (int ks = 0; ks < 2; ks++) {
            const int kc = 2 * ks + lkc;
            const uint32_t csw = (uint32_t)((kc ^ swzL) << 4);

            uint32_t ab[4][4], as_[4][4];
#pragma unroll
            for (int mi = 0; mi < 4; mi++) {
                uint32_t ro = (uint32_t)(mw * 64 + mi * 16 + lro) * 64 + csw;
                ldsm_x4(ab[mi][0], ab[mi][1], ab[mi][2], ab[mi][3], sAb + ro);
                ldsm_x4(as_[mi][0], as_[mi][1], as_[mi][2], as_[mi][3], sAs + ro);
            }
            uint32_t bbg[2][4], bsm[2][4];
#pragma unroll
            for (int fp = 0; fp < 2; fp++) {
                uint32_t ro = (uint32_t)(nw * 32 + fp * 16 + lro) * 64 + csw;
                ldsm_x4(bbg[fp][0], bbg[fp][1], bbg[fp][2], bbg[fp][3], sBb + ro);
                ldsm_x4(bsm[fp][0], bsm[fp][1], bsm[fp][2], bsm[fp][3], sBs + ro);
            }
#pragma unroll
            for (int fp = 0; fp < 2; fp++) {
#pragma unroll
                for (int sub = 0; sub < 2; sub++) {
                    const int f = fp * 2 + sub;
                    const uint32_t b0g = bbg[fp][sub], b1g = bbg[fp][2 + sub];
                    const uint32_t b0s = bsm[fp][sub], b1s = bsm[fp][2 + sub];
#pragma unroll
                    for (int mi = 0; mi < 4; mi++) {
                        MMA_BF16(acc[mi][f], ab[mi][0], ab[mi][1], ab[mi][2], ab[mi][3], b0g, b1g);
                        MMA_BF16(acc[mi][f], as_[mi][0], as_[mi][1], as_[mi][2], as_[mi][3], b0g, b1g);
                        MMA_BF16(acc[mi][f], ab[mi][0], ab[mi][1], ab[mi][2], ab[mi][3], b0s, b1s);
                    }
                }
            }
        }
    }

#pragma unroll
    for (int f = 0; f < 4; f++) {
        const int c = j0 + nw * 32 + f * 8 + tg * 2;
        const float bw0 = bWp[c];
        const float bw1 = bWp[c + 1];
        const int h = c >> 8;
        const int o = c & 255;
#pragma unroll
        for (int mi = 0; mi < 4; mi++) {
            int r0 = m0 + mw * 64 + mi * 16 + g;
            int b0i = r0 >> 10, n0i = r0 & 1023;
            int r1 = r0 + 8;
            int b1i = r1 >> 10, n1i = r1 & 1023;
            float2 v0, v1;
            v0.x = acc[mi][f][0] + bw0; v0.y = acc[mi][f][1] + bw1;
            v1.x = acc[mi][f][2] + bw0; v1.y = acc[mi][f][3] + bw1;
            size_t i0 = ((size_t)(b0i * HH + h) * NN + n0i) * FOUT + o;
            size_t i1 = ((size_t)(b1i * HH + h) * NN + n1i) * FOUT + o;
            *(float2*)(g_Wh + i0) = v0;
            *(float2*)(g_Wh + i1) = v1;
            uint32_t u0, u1;
            PACK_BF16X2(u0, v0.x, v0.y);
            PACK_BF16X2(u1, v1.x, v1.y);
            *(uint32_t*)((char*)g_Whb + i0 * 2) = u0;
            *(uint32_t*)((char*)g_Whb + i1 * 2) = u1;
        }
    }
}

// ---------------------------------------------------------------------------
// Kernel 2: ei / ejb projections (unchanged)
// ---------------------------------------------------------------------------
__global__ void __launch_bounds__(256) score_kernel(const float* __restrict__ a1,
                                                    const float* __restrict__ a2,
                                                    const float* __restrict__ bA)
{
    const int warp = threadIdx.x >> 5;
    const int lane = threadIdx.x & 31;
    const int row = blockIdx.x * 8 + warp;
    const int h = (row >> 10) & (HH - 1);

    const float4* wr = (const float4*)(g_Wh + (size_t)row * FOUT);
    const float4* p1 = (const float4*)(a1 + h * FOUT);
    const float4* p2 = (const float4*)(a2 + h * FOUT);

    float s1 = 0.f, s2 = 0.f;
#pragma unroll
    for (int u = 0; u < 2; u++) {
        float4 v = wr[lane + u * 32];
        float4 x = p1[lane + u * 32];
        float4 y = p2[lane + u * 32];
        s1 += v.x * x.x + v.y * x.y + v.z * x.z + v.w * x.w;
        s2 += v.x * y.x + v.y * y.y + v.z * y.z + v.w * y.w;
    }
#pragma unroll
    for (int off = 16; off > 0; off >>= 1) {
        s1 += __shfl_xor_sync(0xffffffffu, s1, off);
        s2 += __shfl_xor_sync(0xffffffffu, s2, off);
    }
    if (lane == 0) {
        g_ei[row] = s1;
        g_ejb[row] = s2 + bA[h];
    }
}

// ---------------------------------------------------------------------------
// Kernel 3 (fused): per-bh sorted prefix-scan attention, all in one block.
// Thread tid owns output column o = tid. Exact same algebra as the validated
// R9 scan, but prefix state lives in registers; rows emitted inline.
// ---------------------------------------------------------------------------
__device__ __forceinline__ void emit_row(float* __restrict__ out,
                                         int b, int h, int i, int tid,
                                         float Ai, float Bi,
                                         float Utot, float prefU, float prefV,
                                         float ustot, float prefus, float prefvs)
{
    float l = Ai * (ustot - prefus) + Bi * prefvs;
    float x = __fdividef(Ai * (Utot - prefU) + Bi * prefV, l);
    x = fmaxf(x, 0.f);
    float y = __fdividef(1.f, 1.f + __expf(-x));
    out[(size_t)(b * NN + i) * (HH * FOUT) + h * FOUT + tid] = y;
}

__global__ void __launch_bounds__(256) attn_scan_kernel(float* __restrict__ out)
{
    __shared__ float skey[1024];
    __shared__ int   sidx[1024];
    __shared__ float ikey[1024];
    __shared__ int   iidx[1024];
    __shared__ float su[1024], sv[1024];
    __shared__ float sAi[1024], sBi[1024];
    __shared__ int   ss[1024];

    const int bh = blockIdx.x;
    const int tid = threadIdx.x;

    for (int t = tid; t < 1024; t += 256) {
        skey[t] = g_ejb[bh * 1024 + t];  sidx[t] = t;
        ikey[t] = -g_ei[bh * 1024 + t];  iidx[t] = t;
    }
    __syncthreads();

    // fused bitonic sorts: skey ascending (ej), ikey ascending (-ei)
    for (int k = 2; k <= 1024; k <<= 1) {
        for (int j = k >> 1; j > 0; j >>= 1) {
            for (int t = tid; t < 1024; t += 256) {
                int p = t ^ j;
                if (p > t) {
                    bool up = ((t & k) == 0);
                    float a = skey[t], bv = skey[p];
                    if ((a > bv) == up) {
                        skey[t] = bv; skey[p] = a;
                        int ia = sidx[t]; sidx[t] = sidx[p]; sidx[p] = ia;
                    }
                    float c = ikey[t], d = ikey[p];
                    if ((c > d) == up) {
                        ikey[t] = d; ikey[p] = c;
                        int ib = iidx[t]; iidx[t] = iidx[p]; iidx[p] = ib;
                    }
                }
            }
            __syncthreads();
        }
    }

    // per-rank exps and per-row (Ai, Bi, split point s)
    for (int t = tid; t < 1024; t += 256) {
        float e = skey[t];
        su[t] = __expf(e);
        sv[t] = __expf(ALPHA * e);
        float ei = -ikey[t];
        sAi[t] = __expf(ei);
        sBi[t] = __expf(ALPHA * ei);
        float thr = ikey[t];                 // -ei
        int lo = 0, hi = 1024;
        while (lo < hi) {
            int mid = (lo + hi) >> 1;
            if (skey[mid] <= thr) lo = mid + 1; else hi = mid;
        }
        ss[t] = lo;                          // monotone nondecreasing in t
    }
    __syncthreads();

    const __nv_bfloat16* wb = g_Whb + (size_t)bh * (NN * FOUT);

    // pass A: U_total (vector per thread-column) + usum_total (scalar)
    float ut0 = 0.f, ut1 = 0.f, ut2 = 0.f, ut3 = 0.f, ustot = 0.f;
    for (int r = 0; r < 1024; r += 4) {
        float w0 = __bfloat162float(wb[(size_t)sidx[r]     * FOUT + tid]);
        float w1 = __bfloat162float(wb[(size_t)sidx[r + 1] * FOUT + tid]);
        float w2 = __bfloat162float(wb[(size_t)sidx[r + 2] * FOUT + tid]);
        float w3 = __bfloat162float(wb[(size_t)sidx[r + 3] * FOUT + tid]);
        ut0 = fmaf(su[r],     w0, ut0);
        ut1 = fmaf(su[r + 1], w1, ut1);
        ut2 = fmaf(su[r + 2], w2, ut2);
        ut3 = fmaf(su[r + 3], w3, ut3);
        ustot += su[r] + su[r + 1] + su[r + 2] + su[r + 3];
    }
    const float Utot = (ut0 + ut1) + (ut2 + ut3);

    // pass B: sequential prefix sweep + inline emission
    const int b = bh >> 3, h = bh & 7;
    float prefU = 0.f, prefV = 0.f, prefus = 0.f, prefvs = 0.f;
    int ep = 0;

    while (ep < 1024 && ss[ep] == 0) {       // rows entirely in U branch
        emit_row(out, b, h, iidx[ep], tid, sAi[ep], sBi[ep],
                 Utot, prefU, prefV, ustot, prefus, prefvs);
        ep++;
    }

    float wc = __bfloat162float(wb[(size_t)sidx[0] * FOUT + tid]);
    for (int r = 0; r < 1024; r++) {
        float wn = 0.f;
        if (r < 1023)
            wn = __bfloat162float(wb[(size_t)sidx[r + 1] * FOUT + tid]);
        prefU = fmaf(su[r], wc, prefU);
        prefV = fmaf(sv[r], wc, prefV);
        prefus += su[r];
        prefvs += sv[r];
        while (ep < 1024 && ss[ep] == r + 1) {
            emit_row(out, b, h, iidx[ep], tid, sAi[ep], sBi[ep],
                     Utot, prefU, prefV, ustot, prefus, prefvs);
            ep++;
        }
        wc = wn;
    }
}

// ---------------------------------------------------------------------------
extern "C" void kernel_launch(void* const* d_in, const int* in_sizes, int n_in,
                              void* d_out, int out_size)
{
    (void)in_sizes; (void)n_in; (void)out_size;
    const float* h_in = (const float*)d_in[0];
    const float* W    = (const float*)d_in[1];
    const float* bW   = (const float*)d_in[2];
    const float* a1   = (const float*)d_in[3];
    const float* a2   = (const float*)d_in[4];
    const float* bA   = (const float*)d_in[5];
    float* out = (float*)d_out;

    split_h_kernel<<<16384, 256>>>(h_in);
    split_w_kernel<<<2048, 256>>>(W);

    cudaFuncSetAttribute(gemm1_cp_kernel,
                         cudaFuncAttributeMaxDynamicSharedMemorySize, G1_SMEM);
    gemm1_cp_kernel<<<dim3(128, 16), 256, G1_SMEM>>>(bW);

    score_kernel<<<(BB * HH * NN) / 8, 256>>>(a1, a2, bA);

    attn_scan_kernel<<<BB * HH, 256>>>(out);
}